// round 1
// baseline (speedup 1.0000x reference)
#include <cuda_runtime.h>
#include <cuda_bf16.h>
#include <mma.h>

using namespace nvcuda;

// Problem dims
#define BATCH 8
#define CCH   256
#define HH    128
#define WW    128
#define QKD   64
#define HW    (HH*WW)          // 16384
#define MTOT  384              // 64 Q + 64 K + 256 V rows

// ---------------- scratch (static device globals; no allocation) ----------------
__device__ __align__(16) __nv_bfloat16 g_xbf[(size_t)BATCH*CCH*HW];     // 67 MB
__device__ __align__(16) __nv_bfloat16 g_qkv[(size_t)BATCH*MTOT*HW];    // 100 MB
__device__ __align__(16) __nv_bfloat16 g_wc[MTOT*CCH];
__device__ float g_bias[MTOT];

// ---------------- pass 0a: convert x to bf16 ----------------
__global__ void cvt_x_kernel(const float4* __restrict__ x) {
    const int n4 = (BATCH*CCH*HW)/4;   // 8388608
    for (int i = blockIdx.x*blockDim.x + threadIdx.x; i < n4; i += gridDim.x*blockDim.x) {
        float4 v = x[i];
        __nv_bfloat162 lo = __floats2bfloat162_rn(v.x, v.y);
        __nv_bfloat162 hi = __floats2bfloat162_rn(v.z, v.w);
        uint2 u;
        u.x = *reinterpret_cast<unsigned int*>(&lo);
        u.y = *reinterpret_cast<unsigned int*>(&hi);
        reinterpret_cast<uint2*>(g_xbf)[i] = u;
    }
}

// ---------------- pass 0b: fuse weights + biases ----------------
__global__ void prep_w_kernel(const float* __restrict__ wq, const float* __restrict__ bq,
                              const float* __restrict__ wk, const float* __restrict__ bk,
                              const float* __restrict__ wv, const float* __restrict__ bv) {
    int i = blockIdx.x*blockDim.x + threadIdx.x;
    if (i < MTOT*CCH) {
        int row = i / CCH, col = i % CCH;
        float w;
        if (row < 64)       w = wq[row*CCH + col];
        else if (row < 128) w = wk[(row-64)*CCH + col];
        else                w = wv[(row-128)*CCH + col];
        g_wc[i] = __float2bfloat16(w);
    }
    if (i < MTOT) {
        float b;
        if (i < 64)       b = bq[i];
        else if (i < 128) b = bk[i-64];
        else              b = bv[i-128];
        g_bias[i] = b;
    }
}

// ---------------- pass 1: QKV projection GEMM ----------------
// Out[b] (384 x 16384) = Wc (384 x 256) * xbf[b] (256 x 16384) + bias
// CTA tile 64x128, 8 warps (2x4), warp tile 32x32, K-step 64.
#define LDA1 72
#define LDB1 136
#define LDE1 132

__global__ void __launch_bounds__(256) gemm1_kernel() {
    extern __shared__ char sm[];
    __nv_bfloat16* sA = reinterpret_cast<__nv_bfloat16*>(sm);           // 64 x 72
    __nv_bfloat16* sB = reinterpret_cast<__nv_bfloat16*>(sm + 9216);    // 64 x 136
    float*         sE = reinterpret_cast<float*>(sm);                   // 64 x 132 (union)

    const int b  = blockIdx.z;
    const int m0 = blockIdx.y * 64;
    const int n0 = blockIdx.x * 128;
    const int tid = threadIdx.x;
    const int wid = tid >> 5;
    const int wm = wid >> 2, wn = wid & 3;

    const __nv_bfloat16* xb = g_xbf + (size_t)b * CCH * HW;

    wmma::fragment<wmma::accumulator,16,16,16,float> acc[2][2];
    #pragma unroll
    for (int i = 0; i < 2; i++)
        #pragma unroll
        for (int j = 0; j < 2; j++) wmma::fill_fragment(acc[i][j], 0.0f);

    for (int k0 = 0; k0 < CCH; k0 += 64) {
        // A tile: 64x64 bf16 = 512 int4
        for (int c = tid; c < 512; c += 256) {
            int r = c >> 3, c16 = c & 7;
            *reinterpret_cast<int4*>(sA + r*LDA1 + c16*8) =
                *reinterpret_cast<const int4*>(g_wc + (m0 + r)*CCH + k0 + c16*8);
        }
        // B tile: 64x128 bf16 = 1024 int4
        for (int c = tid; c < 1024; c += 256) {
            int r = c >> 4, c16 = c & 15;
            *reinterpret_cast<int4*>(sB + r*LDB1 + c16*8) =
                *reinterpret_cast<const int4*>(xb + (size_t)(k0 + r)*HW + n0 + c16*8);
        }
        __syncthreads();
        #pragma unroll
        for (int kk = 0; kk < 64; kk += 16) {
            wmma::fragment<wmma::matrix_a,16,16,16,__nv_bfloat16,wmma::row_major> af[2];
            wmma::fragment<wmma::matrix_b,16,16,16,__nv_bfloat16,wmma::row_major> bf[2];
            #pragma unroll
            for (int i = 0; i < 2; i++)
                wmma::load_matrix_sync(af[i], sA + (wm*32 + i*16)*LDA1 + kk, LDA1);
            #pragma unroll
            for (int j = 0; j < 2; j++)
                wmma::load_matrix_sync(bf[j], sB + kk*LDB1 + wn*32 + j*16, LDB1);
            #pragma unroll
            for (int i = 0; i < 2; i++)
                #pragma unroll
                for (int j = 0; j < 2; j++)
                    wmma::mma_sync(acc[i][j], af[i], bf[j], acc[i][j]);
        }
        __syncthreads();
    }

    // epilogue: accum -> smem fp32 -> +bias -> bf16 global
    #pragma unroll
    for (int i = 0; i < 2; i++)
        #pragma unroll
        for (int j = 0; j < 2; j++)
            wmma::store_matrix_sync(sE + (wm*32 + i*16)*LDE1 + wn*32 + j*16,
                                    acc[i][j], LDE1, wmma::mem_row_major);
    __syncthreads();

    __nv_bfloat16* outp = g_qkv + ((size_t)b*MTOT + m0)*HW + n0;
    for (int i = tid; i < 64*128; i += 256) {
        int r = i >> 7, cc = i & 127;
        float v = sE[r*LDE1 + cc] + g_bias[m0 + r];
        outp[(size_t)r*HW + cc] = __float2bfloat16(v);
    }
}

// ---------------- pass 2: per-(b,h) row attention ----------------
// smem layout:
//   [0, 34816)            : sQ (64x136 bf16) + sK (64x136 bf16);  later reused as sAt (128x136 bf16)
//   [34816, 102400)       : sS (128x132 fp32); later reused as sO (64x132 fp32)
//   [102400, 119808)      : sV (64x136 bf16)
#define LDQ 136
#define LDS 132
#define ATTN_SMEM 119808

__global__ void __launch_bounds__(256) attn_kernel(const float* __restrict__ x,
                                                   const float* __restrict__ gamma,
                                                   float* __restrict__ y) {
    extern __shared__ char sm[];
    __nv_bfloat16* sQ  = reinterpret_cast<__nv_bfloat16*>(sm);
    __nv_bfloat16* sK  = sQ + 64*LDQ;
    __nv_bfloat16* sAt = reinterpret_cast<__nv_bfloat16*>(sm);          // 128x136 (overlaps Q,K)
    float*         sS  = reinterpret_cast<float*>(sm + 34816);          // 128x132
    float*         sO  = sS;                                            // 64x132 (reuse)
    __nv_bfloat16* sV  = reinterpret_cast<__nv_bfloat16*>(sm + 102400); // 64x136

    const int bh = blockIdx.x;
    const int b = bh >> 7, h = bh & 127;
    const int tid = threadIdx.x;
    const int wid = tid >> 5, lane = tid & 31;

    const __nv_bfloat16* qbase = g_qkv + (size_t)b*MTOT*HW + h*WW;

    // load Q (rows 0..63) and K (rows 64..127)
    for (int c = tid; c < 1024; c += 256) {
        int r = c >> 4, c16 = c & 15;
        *reinterpret_cast<int4*>(sQ + r*LDQ + c16*8) =
            *reinterpret_cast<const int4*>(qbase + (size_t)r*HW + c16*8);
    }
    for (int c = tid; c < 1024; c += 256) {
        int r = c >> 4, c16 = c & 15;
        *reinterpret_cast<int4*>(sK + r*LDQ + c16*8) =
            *reinterpret_cast<const int4*>(qbase + (size_t)(64 + r)*HW + c16*8);
    }
    __syncthreads();

    // GEMM2: S(128x128) = Q^T * K ; warps 2x4, warp tile 64x32
    {
        const int wm = wid >> 2, wn = wid & 3;
        wmma::fragment<wmma::accumulator,16,16,16,float> acc[4][2];
        #pragma unroll
        for (int i = 0; i < 4; i++)
            #pragma unroll
            for (int j = 0; j < 2; j++) wmma::fill_fragment(acc[i][j], 0.0f);
        #pragma unroll
        for (int kk = 0; kk < QKD; kk += 16) {
            wmma::fragment<wmma::matrix_a,16,16,16,__nv_bfloat16,wmma::col_major> af[4];
            wmma::fragment<wmma::matrix_b,16,16,16,__nv_bfloat16,wmma::row_major> bf[2];
            #pragma unroll
            for (int i = 0; i < 4; i++)
                wmma::load_matrix_sync(af[i], sQ + kk*LDQ + wm*64 + i*16, LDQ);
            #pragma unroll
            for (int j = 0; j < 2; j++)
                wmma::load_matrix_sync(bf[j], sK + kk*LDQ + wn*32 + j*16, LDQ);
            #pragma unroll
            for (int i = 0; i < 4; i++)
                #pragma unroll
                for (int j = 0; j < 2; j++)
                    wmma::mma_sync(acc[i][j], af[i], bf[j], acc[i][j]);
        }
        #pragma unroll
        for (int i = 0; i < 4; i++)
            #pragma unroll
            for (int j = 0; j < 2; j++)
                wmma::store_matrix_sync(sS + (wm*64 + i*16)*LDS + wn*32 + j*16,
                                        acc[i][j], LDS, wmma::mem_row_major);
    }
    __syncthreads();

    // softmax over keys (row-wise); write bf16 attn into sAt (overwrites Q/K)
    for (int r = wid; r < 128; r += 8) {
        float v0 = sS[r*LDS + lane];
        float v1 = sS[r*LDS + lane + 32];
        float v2 = sS[r*LDS + lane + 64];
        float v3 = sS[r*LDS + lane + 96];
        float mx = fmaxf(fmaxf(v0, v1), fmaxf(v2, v3));
        #pragma unroll
        for (int o = 16; o > 0; o >>= 1) mx = fmaxf(mx, __shfl_xor_sync(0xffffffffu, mx, o));
        v0 = __expf(v0 - mx); v1 = __expf(v1 - mx);
        v2 = __expf(v2 - mx); v3 = __expf(v3 - mx);
        float s = v0 + v1 + v2 + v3;
        #pragma unroll
        for (int o = 16; o > 0; o >>= 1) s += __shfl_xor_sync(0xffffffffu, s, o);
        float inv = 1.0f / s;
        sAt[r*LDQ + lane]      = __float2bfloat16(v0*inv);
        sAt[r*LDQ + lane + 32] = __float2bfloat16(v1*inv);
        sAt[r*LDQ + lane + 64] = __float2bfloat16(v2*inv);
        sAt[r*LDQ + lane + 96] = __float2bfloat16(v3*inv);
    }
    __syncthreads();

    const float g = gamma[0];

    // GEMM3 in 64-channel chunks: O(64x128) = V_chunk(64x128) * attn^T
    for (int c0 = 0; c0 < CCH; c0 += 64) {
        for (int c = tid; c < 1024; c += 256) {
            int r = c >> 4, c16 = c & 15;
            *reinterpret_cast<int4*>(sV + r*LDQ + c16*8) =
                *reinterpret_cast<const int4*>(qbase + (size_t)(128 + c0 + r)*HW + c16*8);
        }
        __syncthreads();

        const int wm = wid >> 2, wn = wid & 3;   // warps 2x4, warp tile 32x32
        wmma::fragment<wmma::accumulator,16,16,16,float> acc[2][2];
        #pragma unroll
        for (int i = 0; i < 2; i++)
            #pragma unroll
            for (int j = 0; j < 2; j++) wmma::fill_fragment(acc[i][j], 0.0f);
        #pragma unroll
        for (int kk = 0; kk < 128; kk += 16) {
            wmma::fragment<wmma::matrix_a,16,16,16,__nv_bfloat16,wmma::row_major> af[2];
            wmma::fragment<wmma::matrix_b,16,16,16,__nv_bfloat16,wmma::col_major> bf[2];
            #pragma unroll
            for (int i = 0; i < 2; i++)
                wmma::load_matrix_sync(af[i], sV + (wm*32 + i*16)*LDQ + kk, LDQ);
            #pragma unroll
            for (int j = 0; j < 2; j++)
                wmma::load_matrix_sync(bf[j], sAt + (wn*32 + j*16)*LDQ + kk, LDQ);
            #pragma unroll
            for (int i = 0; i < 2; i++)
                #pragma unroll
                for (int j = 0; j < 2; j++)
                    wmma::mma_sync(acc[i][j], af[i], bf[j], acc[i][j]);
        }
        #pragma unroll
        for (int i = 0; i < 2; i++)
            #pragma unroll
            for (int j = 0; j < 2; j++)
                wmma::store_matrix_sync(sO + (wm*32 + i*16)*LDS + wn*32 + j*16,
                                        acc[i][j], LDS, wmma::mem_row_major);
        __syncthreads();

        const float* xb = x + (((size_t)b*CCH + c0)*HH + h)*WW;
        float*       yb = y + (((size_t)b*CCH + c0)*HH + h)*WW;
        for (int i = tid; i < 64*128; i += 256) {
            int r = i >> 7, cc = i & 127;
            float v = g * sO[r*LDS + cc] + xb[(size_t)r*HW + cc];
            yb[(size_t)r*HW + cc] = v;
        }
        __syncthreads();
    }
}

// ---------------- launch ----------------
extern "C" void kernel_launch(void* const* d_in, const int* in_sizes, int n_in,
                              void* d_out, int out_size) {
    const float* x     = (const float*)d_in[0];
    const float* wq    = (const float*)d_in[1];
    const float* bq    = (const float*)d_in[2];
    const float* wk    = (const float*)d_in[3];
    const float* bk    = (const float*)d_in[4];
    const float* wv    = (const float*)d_in[5];
    const float* bv    = (const float*)d_in[6];
    const float* gamma = (const float*)d_in[7];
    float* y = (float*)d_out;

    cvt_x_kernel<<<8192, 256>>>(reinterpret_cast<const float4*>(x));
    prep_w_kernel<<<(MTOT*CCH + 255)/256, 256>>>(wq, bq, wk, bk, wv, bv);

    dim3 g1(HW/128, MTOT/64, BATCH);
    gemm1_kernel<<<g1, 256, 33792>>>();

    cudaFuncSetAttribute(attn_kernel, cudaFuncAttributeMaxDynamicSharedMemorySize, ATTN_SMEM);
    attn_kernel<<<BATCH*HH, 256, ATTN_SMEM>>>(x, gamma, y);
}

// round 2
// speedup vs baseline: 1.8223x; 1.8223x over previous
#include <cuda_runtime.h>
#include <cuda_bf16.h>
#include <mma.h>

using namespace nvcuda;

#define BATCH 8
#define CCH   256
#define HH    128
#define WW    128
#define QKD   64
#define HW    (HH*WW)
#define MTOT  384

// ---------------- scratch ----------------
__device__ __align__(16) __nv_bfloat16 g_qkv[(size_t)BATCH*MTOT*HW];    // 100 MB
__device__ __align__(16) __nv_bfloat16 g_wc[MTOT*CCH];
__device__ float g_bias[MTOT];

// ---------------- prep: fuse weights + biases ----------------
__global__ void prep_w_kernel(const float* __restrict__ wq, const float* __restrict__ bq,
                              const float* __restrict__ wk, const float* __restrict__ bk,
                              const float* __restrict__ wv, const float* __restrict__ bv) {
    int i = blockIdx.x*blockDim.x + threadIdx.x;
    if (i < MTOT*CCH) {
        int row = i / CCH, col = i % CCH;
        float w;
        if (row < 64)       w = wq[row*CCH + col];
        else if (row < 128) w = wk[(row-64)*CCH + col];
        else                w = wv[(row-128)*CCH + col];
        g_wc[i] = __float2bfloat16(w);
    }
    if (i < MTOT) {
        float b;
        if (i < 64)       b = bq[i];
        else if (i < 128) b = bk[i-64];
        else              b = bv[i-128];
        g_bias[i] = b;
    }
}

// ---------------- pass 1: QKV projection, fused fp32->bf16 ----------------
// Out[b](384 x 16384) = Wc(384x256) * x[b](256x16384) + bias
// CTA tile 192x128, k-step 32, 8 warps (2x4), warp tile 96x32.
#define LDA1 40
#define LDB1 136
#define LDE1 132
#define G1_SMEM 50688   // max( A 15360 + B 8704, epi 96*132*4 )

__global__ void __launch_bounds__(256) gemm1_kernel(const float* __restrict__ x) {
    extern __shared__ char sm[];
    __nv_bfloat16* sA = reinterpret_cast<__nv_bfloat16*>(sm);            // 192 x 40
    __nv_bfloat16* sB = reinterpret_cast<__nv_bfloat16*>(sm + 15360);    // 32 x 136
    float*         sE = reinterpret_cast<float*>(sm);                    // 96 x 132 (union)

    const int b  = blockIdx.z;
    const int m0 = blockIdx.y * 192;
    const int n0 = blockIdx.x * 128;
    const int tid = threadIdx.x;
    const int wid = tid >> 5;
    const int wm = wid >> 2, wn = wid & 3;

    const float* xb = x + (size_t)b * CCH * HW;

    wmma::fragment<wmma::accumulator,16,16,16,float> acc[6][2];
    #pragma unroll
    for (int i = 0; i < 6; i++)
        #pragma unroll
        for (int j = 0; j < 2; j++) wmma::fill_fragment(acc[i][j], 0.0f);

    for (int k0 = 0; k0 < CCH; k0 += 32) {
        // A tile 192x32 bf16 : 768 int4
        #pragma unroll
        for (int t = 0; t < 3; t++) {
            int idx = tid + t*256; int r = idx >> 2, c = idx & 3;
            *reinterpret_cast<int4*>(sA + r*LDA1 + c*8) =
                *reinterpret_cast<const int4*>(g_wc + (m0 + r)*CCH + k0 + c*8);
        }
        // B tile 32x128 f32 -> bf16 : 1024 float4
        #pragma unroll
        for (int t = 0; t < 4; t++) {
            int idx = tid + t*256; int r = idx >> 5, c = idx & 31;
            float4 v = *reinterpret_cast<const float4*>(xb + (size_t)(k0 + r)*HW + n0 + c*4);
            __nv_bfloat162 lo = __floats2bfloat162_rn(v.x, v.y);
            __nv_bfloat162 hi = __floats2bfloat162_rn(v.z, v.w);
            uint2 u;
            u.x = *reinterpret_cast<unsigned*>(&lo);
            u.y = *reinterpret_cast<unsigned*>(&hi);
            *reinterpret_cast<uint2*>(sB + r*LDB1 + c*4) = u;
        }
        __syncthreads();
        #pragma unroll
        for (int kk = 0; kk < 32; kk += 16) {
            wmma::fragment<wmma::matrix_a,16,16,16,__nv_bfloat16,wmma::row_major> af[6];
            wmma::fragment<wmma::matrix_b,16,16,16,__nv_bfloat16,wmma::row_major> bf[2];
            #pragma unroll
            for (int i = 0; i < 6; i++)
                wmma::load_matrix_sync(af[i], sA + (wm*96 + i*16)*LDA1 + kk, LDA1);
            #pragma unroll
            for (int j = 0; j < 2; j++)
                wmma::load_matrix_sync(bf[j], sB + kk*LDB1 + wn*32 + j*16, LDB1);
            #pragma unroll
            for (int i = 0; i < 6; i++)
                #pragma unroll
                for (int j = 0; j < 2; j++)
                    wmma::mma_sync(acc[i][j], af[i], bf[j], acc[i][j]);
        }
        __syncthreads();
    }

    // epilogue: two 96-row halves through smem
    #pragma unroll
    for (int half = 0; half < 2; half++) {
        if (wm == half) {
            #pragma unroll
            for (int i = 0; i < 6; i++)
                #pragma unroll
                for (int j = 0; j < 2; j++)
                    wmma::store_matrix_sync(sE + (i*16)*LDE1 + wn*32 + j*16,
                                            acc[i][j], LDE1, wmma::mem_row_major);
        }
        __syncthreads();
        #pragma unroll
        for (int t = 0; t < 24; t++) {
            int idx = tid + t*256;                 // 0..6143 (96 rows x 64 pairs)
            int r = idx >> 6, c2 = (idx & 63) * 2;
            int grow = m0 + half*96 + r;
            float bias = g_bias[grow];
            float v0 = sE[r*LDE1 + c2]     + bias;
            float v1 = sE[r*LDE1 + c2 + 1] + bias;
            __nv_bfloat162 o = __floats2bfloat162_rn(v0, v1);
            *reinterpret_cast<unsigned*>(g_qkv + ((size_t)b*MTOT + grow)*HW + n0 + c2) =
                *reinterpret_cast<unsigned*>(&o);
        }
        __syncthreads();
    }
}

// ---------------- pass 2: row attention (register softmax, raw mma) ----------------
#define LDQ 136
#define ATTN_SMEM 69632   // Q(64x136) + K(64x136) + 2x V(64x136), bf16

__device__ __forceinline__ void mma16816(float* d, const unsigned* a, unsigned b0, unsigned b1) {
    asm volatile("mma.sync.aligned.m16n8k16.row.col.f32.bf16.bf16.f32 "
        "{%0,%1,%2,%3}, {%4,%5,%6,%7}, {%8,%9}, {%0,%1,%2,%3};\n"
        : "+f"(d[0]), "+f"(d[1]), "+f"(d[2]), "+f"(d[3])
        : "r"(a[0]), "r"(a[1]), "r"(a[2]), "r"(a[3]), "r"(b0), "r"(b1));
}

__device__ __forceinline__ void cpasync16(void* smem_dst, const void* gptr) {
    unsigned s = (unsigned)__cvta_generic_to_shared(smem_dst);
    asm volatile("cp.async.cg.shared.global [%0], [%1], 16;\n" :: "r"(s), "l"(gptr));
}

__device__ __forceinline__ unsigned pack_bf16(float lo, float hi) {
    __nv_bfloat162 t = __floats2bfloat162_rn(lo, hi);
    return *reinterpret_cast<unsigned*>(&t);
}

__global__ void __launch_bounds__(256, 2) attn_kernel(const float* __restrict__ x,
                                                      const float* __restrict__ gamma,
                                                      float* __restrict__ y) {
    extern __shared__ char sm[];
    __nv_bfloat16* sQ  = reinterpret_cast<__nv_bfloat16*>(sm);
    __nv_bfloat16* sK  = sQ  + 64*LDQ;
    __nv_bfloat16* sV0 = sK  + 64*LDQ;
    __nv_bfloat16* sV1 = sV0 + 64*LDQ;
    const unsigned short* sQh = reinterpret_cast<const unsigned short*>(sQ);
    const unsigned short* sKh = reinterpret_cast<const unsigned short*>(sK);

    const int bh = blockIdx.x;
    const int b = bh >> 7, h = bh & 127;
    const int tid = threadIdx.x, wid = tid >> 5, lane = tid & 31;
    const __nv_bfloat16* qbase = g_qkv + (size_t)b*MTOT*HW + h*WW;

    // async load Q, K, V-chunk0
    #pragma unroll
    for (int t = 0; t < 4; t++) {
        int idx = tid + t*256; int r = idx >> 4, c = idx & 15;
        cpasync16(sQ  + r*LDQ + c*8, qbase + (size_t)r*HW + c*8);
        cpasync16(sK  + r*LDQ + c*8, qbase + (size_t)(64 + r)*HW + c*8);
        cpasync16(sV0 + r*LDQ + c*8, qbase + (size_t)(128 + r)*HW + c*8);
    }
    asm volatile("cp.async.commit_group;\n");
    asm volatile("cp.async.wait_group 0;\n");
    __syncthreads();

    const int w0 = wid * 16;            // this warp's 16 query pixels
    const int r4 = lane >> 2;           // groupID
    const int c2 = (lane & 3) * 2;

    // ---- S = Q^T K  (per-warp 16 x 128 accumulator) ----
    float sacc[16][4];
    #pragma unroll
    for (int nb = 0; nb < 16; nb++) {
        sacc[nb][0] = 0.f; sacc[nb][1] = 0.f; sacc[nb][2] = 0.f; sacc[nb][3] = 0.f;
    }

    #pragma unroll
    for (int kb = 0; kb < 4; kb++) {
        const int kr = kb*16 + c2;
        unsigned a[4];
        a[0] = (unsigned)sQh[ kr   *LDQ + w0 + r4    ] | ((unsigned)sQh[(kr+1)*LDQ + w0 + r4    ] << 16);
        a[1] = (unsigned)sQh[ kr   *LDQ + w0 + r4 + 8] | ((unsigned)sQh[(kr+1)*LDQ + w0 + r4 + 8] << 16);
        a[2] = (unsigned)sQh[(kr+8)*LDQ + w0 + r4    ] | ((unsigned)sQh[(kr+9)*LDQ + w0 + r4    ] << 16);
        a[3] = (unsigned)sQh[(kr+8)*LDQ + w0 + r4 + 8] | ((unsigned)sQh[(kr+9)*LDQ + w0 + r4 + 8] << 16);
        #pragma unroll
        for (int nb = 0; nb < 16; nb++) {
            const int nc = nb*8 + r4;
            unsigned b0 = (unsigned)sKh[ kr   *LDQ + nc] | ((unsigned)sKh[(kr+1)*LDQ + nc] << 16);
            unsigned b1 = (unsigned)sKh[(kr+8)*LDQ + nc] | ((unsigned)sKh[(kr+9)*LDQ + nc] << 16);
            mma16816(sacc[nb], a, b0, b1);
        }
    }

    // ---- register softmax over 128 keys (rows r4 and r4+8 of warp tile) ----
    float mx0 = -1e30f, mx1 = -1e30f;
    #pragma unroll
    for (int nb = 0; nb < 16; nb++) {
        mx0 = fmaxf(mx0, fmaxf(sacc[nb][0], sacc[nb][1]));
        mx1 = fmaxf(mx1, fmaxf(sacc[nb][2], sacc[nb][3]));
    }
    mx0 = fmaxf(mx0, __shfl_xor_sync(0xffffffffu, mx0, 1));
    mx0 = fmaxf(mx0, __shfl_xor_sync(0xffffffffu, mx0, 2));
    mx1 = fmaxf(mx1, __shfl_xor_sync(0xffffffffu, mx1, 1));
    mx1 = fmaxf(mx1, __shfl_xor_sync(0xffffffffu, mx1, 2));
    float s0 = 0.f, s1 = 0.f;
    #pragma unroll
    for (int nb = 0; nb < 16; nb++) {
        sacc[nb][0] = __expf(sacc[nb][0] - mx0);
        sacc[nb][1] = __expf(sacc[nb][1] - mx0);
        sacc[nb][2] = __expf(sacc[nb][2] - mx1);
        sacc[nb][3] = __expf(sacc[nb][3] - mx1);
        s0 += sacc[nb][0] + sacc[nb][1];
        s1 += sacc[nb][2] + sacc[nb][3];
    }
    s0 += __shfl_xor_sync(0xffffffffu, s0, 1);
    s0 += __shfl_xor_sync(0xffffffffu, s0, 2);
    s1 += __shfl_xor_sync(0xffffffffu, s1, 1);
    s1 += __shfl_xor_sync(0xffffffffu, s1, 2);
    const float inv0 = 1.0f / s0, inv1 = 1.0f / s1;

    // repack probs into A fragments for O = attn * V^T
    unsigned ap[8][4];
    #pragma unroll
    for (int kb = 0; kb < 8; kb++) {
        ap[kb][0] = pack_bf16(sacc[2*kb  ][0]*inv0, sacc[2*kb  ][1]*inv0);
        ap[kb][1] = pack_bf16(sacc[2*kb  ][2]*inv1, sacc[2*kb  ][3]*inv1);
        ap[kb][2] = pack_bf16(sacc[2*kb+1][0]*inv0, sacc[2*kb+1][1]*inv0);
        ap[kb][3] = pack_bf16(sacc[2*kb+1][2]*inv1, sacc[2*kb+1][3]*inv1);
    }

    const float g = gamma[0];

    // ---- O phase: 4 channel chunks of 64, double-buffered V ----
    #pragma unroll 1
    for (int ci = 0; ci < 4; ci++) {
        const __nv_bfloat16* sV = (ci & 1) ? sV1 : sV0;
        if (ci < 3) {
            __nv_bfloat16* nxt = (ci & 1) ? sV0 : sV1;
            #pragma unroll
            for (int t = 0; t < 4; t++) {
                int idx = tid + t*256; int r = idx >> 4, c = idx & 15;
                cpasync16(nxt + r*LDQ + c*8,
                          qbase + (size_t)(128 + (ci+1)*64 + r)*HW + c*8);
            }
            asm volatile("cp.async.commit_group;\n");
        }
        const unsigned short* sVh = reinterpret_cast<const unsigned short*>(sV);

        float oacc[8][4];
        #pragma unroll
        for (int nb = 0; nb < 8; nb++) {
            oacc[nb][0] = 0.f; oacc[nb][1] = 0.f; oacc[nb][2] = 0.f; oacc[nb][3] = 0.f;
        }
        #pragma unroll
        for (int kb = 0; kb < 8; kb++) {
            #pragma unroll
            for (int nb = 0; nb < 8; nb++) {
                unsigned b0 = *reinterpret_cast<const unsigned*>(sVh + (nb*8 + r4)*LDQ + kb*16 + c2);
                unsigned b1 = *reinterpret_cast<const unsigned*>(sVh + (nb*8 + r4)*LDQ + kb*16 + c2 + 8);
                mma16816(oacc[nb], ap[kb], b0, b1);
            }
        }

        // epilogue: gamma*O + x -> y, straight from registers
        const int c0 = ci * 64;
        #pragma unroll
        for (int nb = 0; nb < 8; nb++) {
            int ch = c0 + nb*8 + c2;
            size_t base = ((size_t)(b*CCH + ch)*HH + h)*WW + w0;
            y[base + r4]          = g*oacc[nb][0] + x[base + r4];
            y[base + HW + r4]     = g*oacc[nb][1] + x[base + HW + r4];
            y[base + r4 + 8]      = g*oacc[nb][2] + x[base + r4 + 8];
            y[base + HW + r4 + 8] = g*oacc[nb][3] + x[base + HW + r4 + 8];
        }

        if (ci < 3) {
            asm volatile("cp.async.wait_group 0;\n");
            __syncthreads();
        }
    }
}

// ---------------- launch ----------------
extern "C" void kernel_launch(void* const* d_in, const int* in_sizes, int n_in,
                              void* d_out, int out_size) {
    const float* x     = (const float*)d_in[0];
    const float* wq    = (const float*)d_in[1];
    const float* bq    = (const float*)d_in[2];
    const float* wk    = (const float*)d_in[3];
    const float* bk    = (const float*)d_in[4];
    const float* wv    = (const float*)d_in[5];
    const float* bv    = (const float*)d_in[6];
    const float* gamma = (const float*)d_in[7];
    float* y = (float*)d_out;

    prep_w_kernel<<<(MTOT*CCH + 255)/256, 256>>>(wq, bq, wk, bk, wv, bv);

    cudaFuncSetAttribute(gemm1_kernel, cudaFuncAttributeMaxDynamicSharedMemorySize, G1_SMEM);
    dim3 g1(HW/128, 2, BATCH);
    gemm1_kernel<<<g1, 256, G1_SMEM>>>(x);

    cudaFuncSetAttribute(attn_kernel, cudaFuncAttributeMaxDynamicSharedMemorySize, ATTN_SMEM);
    attn_kernel<<<BATCH*HH, 256, ATTN_SMEM>>>(x, gamma, y);
}

// round 3
// speedup vs baseline: 1.9258x; 1.0568x over previous
#include <cuda_runtime.h>
#include <cuda_bf16.h>

#define BATCH 8
#define CCH   256
#define HH    128
#define WW    128
#define QKD   64
#define HW    (HH*WW)
#define MTOT  384

// ---------------- scratch ----------------
__device__ __align__(16) __nv_bfloat16 g_wc[MTOT*CCH];
__device__ float g_bias[MTOT];

// ---------------- prep: fuse weights + biases ----------------
__global__ void prep_w_kernel(const float* __restrict__ wq, const float* __restrict__ bq,
                              const float* __restrict__ wk, const float* __restrict__ bk,
                              const float* __restrict__ wv, const float* __restrict__ bv) {
    int i = blockIdx.x*blockDim.x + threadIdx.x;
    if (i < MTOT*CCH) {
        int row = i / CCH, col = i % CCH;
        float w;
        if (row < 64)       w = wq[row*CCH + col];
        else if (row < 128) w = wk[(row-64)*CCH + col];
        else                w = wv[(row-128)*CCH + col];
        g_wc[i] = __float2bfloat16(w);
    }
    if (i < MTOT) {
        float b;
        if (i < 64)       b = bq[i];
        else if (i < 128) b = bk[i-64];
        else              b = bv[i-128];
        g_bias[i] = b;
    }
}

// ---------------- fused kernel ----------------
#define LDX 136
#define LDQ 136
// smem: xs(256x136 bf16)=69632 | sQK(128x136 bf16)=34816 | sV(64x136 bf16)=17408
#define OFF_QK 69632
#define OFF_V  104448
#define FUSED_SMEM 121856

__device__ __forceinline__ void mma16816(float* d, const unsigned* a, unsigned b0, unsigned b1) {
    asm volatile("mma.sync.aligned.m16n8k16.row.col.f32.bf16.bf16.f32 "
        "{%0,%1,%2,%3}, {%4,%5,%6,%7}, {%8,%9}, {%0,%1,%2,%3};\n"
        : "+f"(d[0]), "+f"(d[1]), "+f"(d[2]), "+f"(d[3])
        : "r"(a[0]), "r"(a[1]), "r"(a[2]), "r"(a[3]), "r"(b0), "r"(b1));
}

__device__ __forceinline__ unsigned pack_bf16(float lo, float hi) {
    __nv_bfloat162 t = __floats2bfloat162_rn(lo, hi);
    return *reinterpret_cast<unsigned*>(&t);
}

__global__ void __launch_bounds__(256, 1) fused_kernel(const float* __restrict__ x,
                                                       const float* __restrict__ gamma,
                                                       float* __restrict__ y) {
    extern __shared__ char sm[];
    __nv_bfloat16* xs  = reinterpret_cast<__nv_bfloat16*>(sm);
    __nv_bfloat16* sQK = reinterpret_cast<__nv_bfloat16*>(sm + OFF_QK);   // rows 0..63 Q, 64..127 K
    __nv_bfloat16* sV  = reinterpret_cast<__nv_bfloat16*>(sm + OFF_V);
    const unsigned short* xsh = reinterpret_cast<const unsigned short*>(xs);
    const unsigned short* sQh = reinterpret_cast<const unsigned short*>(sQK);
    const unsigned short* sKh = sQh + 64*LDQ;
    const unsigned short* sVh = reinterpret_cast<const unsigned short*>(sV);

    const int bh = blockIdx.x;
    const int b = bh >> 7, h = bh & 127;
    const int tid = threadIdx.x, wid = tid >> 5, lane = tid & 31;
    const int r4 = lane >> 2;
    const int c2 = (lane & 3) * 2;

    const float* xb = x + (size_t)b*CCH*HW + h*WW;   // channel stride = HW

    // ---- load x slice -> bf16 smem (xs[channel][pixel]) ----
    #pragma unroll
    for (int t = 0; t < 32; t++) {
        int idx = tid + t*256;            // 8192 float4
        int r = idx >> 5, c = idx & 31;
        float4 v = *reinterpret_cast<const float4*>(xb + (size_t)r*HW + c*4);
        __nv_bfloat162 lo = __floats2bfloat162_rn(v.x, v.y);
        __nv_bfloat162 hi = __floats2bfloat162_rn(v.z, v.w);
        uint2 u;
        u.x = *reinterpret_cast<unsigned*>(&lo);
        u.y = *reinterpret_cast<unsigned*>(&hi);
        *reinterpret_cast<uint2*>(xs + r*LDX + c*4) = u;
    }
    __syncthreads();

    // ---- proj Q,K: rows 0..127 of Wc * xs + bias -> sQK[channel][pixel] ----
    {
        const int m0 = wid * 16;
        const unsigned short* w0p = reinterpret_cast<const unsigned short*>(g_wc) + (m0 + r4)*CCH;
        const unsigned short* w1p = w0p + 8*CCH;
        float acc[16][4];
        #pragma unroll
        for (int nb = 0; nb < 16; nb++) { acc[nb][0]=0.f; acc[nb][1]=0.f; acc[nb][2]=0.f; acc[nb][3]=0.f; }
        #pragma unroll
        for (int kb = 0; kb < 16; kb++) {
            unsigned a[4];
            a[0] = *reinterpret_cast<const unsigned*>(w0p + kb*16 + c2);
            a[1] = *reinterpret_cast<const unsigned*>(w1p + kb*16 + c2);
            a[2] = *reinterpret_cast<const unsigned*>(w0p + kb*16 + c2 + 8);
            a[3] = *reinterpret_cast<const unsigned*>(w1p + kb*16 + c2 + 8);
            const int kr = kb*16 + c2;
            #pragma unroll
            for (int nb = 0; nb < 16; nb++) {
                const int n = nb*8 + r4;
                unsigned b0 = (unsigned)xsh[ kr   *LDX + n] | ((unsigned)xsh[(kr+1)*LDX + n] << 16);
                unsigned b1 = (unsigned)xsh[(kr+8)*LDX + n] | ((unsigned)xsh[(kr+9)*LDX + n] << 16);
                mma16816(acc[nb], a, b0, b1);
            }
        }
        const float bias0 = g_bias[m0 + r4], bias1 = g_bias[m0 + r4 + 8];
        #pragma unroll
        for (int nb = 0; nb < 16; nb++) {
            *reinterpret_cast<unsigned*>(sQK + (m0 + r4    )*LDQ + nb*8 + c2) =
                pack_bf16(acc[nb][0] + bias0, acc[nb][1] + bias0);
            *reinterpret_cast<unsigned*>(sQK + (m0 + r4 + 8)*LDQ + nb*8 + c2) =
                pack_bf16(acc[nb][2] + bias1, acc[nb][3] + bias1);
        }
    }
    __syncthreads();

    const int w0 = wid * 16;   // this warp's 16 query pixels

    // ---- S = Q^T K (per-warp 16 x 128) ----
    float sacc[16][4];
    #pragma unroll
    for (int nb = 0; nb < 16; nb++) { sacc[nb][0]=0.f; sacc[nb][1]=0.f; sacc[nb][2]=0.f; sacc[nb][3]=0.f; }

    #pragma unroll
    for (int kb = 0; kb < 4; kb++) {
        const int kr = kb*16 + c2;
        unsigned a[4];
        a[0] = (unsigned)sQh[ kr   *LDQ + w0 + r4    ] | ((unsigned)sQh[(kr+1)*LDQ + w0 + r4    ] << 16);
        a[1] = (unsigned)sQh[ kr   *LDQ + w0 + r4 + 8] | ((unsigned)sQh[(kr+1)*LDQ + w0 + r4 + 8] << 16);
        a[2] = (unsigned)sQh[(kr+8)*LDQ + w0 + r4    ] | ((unsigned)sQh[(kr+9)*LDQ + w0 + r4    ] << 16);
        a[3] = (unsigned)sQh[(kr+8)*LDQ + w0 + r4 + 8] | ((unsigned)sQh[(kr+9)*LDQ + w0 + r4 + 8] << 16);
        #pragma unroll
        for (int nb = 0; nb < 16; nb++) {
            const int nc = nb*8 + r4;
            unsigned b0 = (unsigned)sKh[ kr   *LDQ + nc] | ((unsigned)sKh[(kr+1)*LDQ + nc] << 16);
            unsigned b1 = (unsigned)sKh[(kr+8)*LDQ + nc] | ((unsigned)sKh[(kr+9)*LDQ + nc] << 16);
            mma16816(sacc[nb], a, b0, b1);
        }
    }

    // ---- register softmax over 128 keys ----
    float mx0 = -1e30f, mx1 = -1e30f;
    #pragma unroll
    for (int nb = 0; nb < 16; nb++) {
        mx0 = fmaxf(mx0, fmaxf(sacc[nb][0], sacc[nb][1]));
        mx1 = fmaxf(mx1, fmaxf(sacc[nb][2], sacc[nb][3]));
    }
    mx0 = fmaxf(mx0, __shfl_xor_sync(0xffffffffu, mx0, 1));
    mx0 = fmaxf(mx0, __shfl_xor_sync(0xffffffffu, mx0, 2));
    mx1 = fmaxf(mx1, __shfl_xor_sync(0xffffffffu, mx1, 1));
    mx1 = fmaxf(mx1, __shfl_xor_sync(0xffffffffu, mx1, 2));
    float s0 = 0.f, s1 = 0.f;
    #pragma unroll
    for (int nb = 0; nb < 16; nb++) {
        sacc[nb][0] = __expf(sacc[nb][0] - mx0);
        sacc[nb][1] = __expf(sacc[nb][1] - mx0);
        sacc[nb][2] = __expf(sacc[nb][2] - mx1);
        sacc[nb][3] = __expf(sacc[nb][3] - mx1);
        s0 += sacc[nb][0] + sacc[nb][1];
        s1 += sacc[nb][2] + sacc[nb][3];
    }
    s0 += __shfl_xor_sync(0xffffffffu, s0, 1);
    s0 += __shfl_xor_sync(0xffffffffu, s0, 2);
    s1 += __shfl_xor_sync(0xffffffffu, s1, 1);
    s1 += __shfl_xor_sync(0xffffffffu, s1, 2);
    const float inv0 = 1.0f / s0, inv1 = 1.0f / s1;

    unsigned ap[8][4];
    #pragma unroll
    for (int kb = 0; kb < 8; kb++) {
        ap[kb][0] = pack_bf16(sacc[2*kb  ][0]*inv0, sacc[2*kb  ][1]*inv0);
        ap[kb][1] = pack_bf16(sacc[2*kb  ][2]*inv1, sacc[2*kb  ][3]*inv1);
        ap[kb][2] = pack_bf16(sacc[2*kb+1][0]*inv0, sacc[2*kb+1][1]*inv0);
        ap[kb][3] = pack_bf16(sacc[2*kb+1][2]*inv1, sacc[2*kb+1][3]*inv1);
    }

    const float g = gamma[0];

    // ---- 4 chunks of 64 V channels: proj V -> sV, then O = attn * V^T ----
    const int vm = wid >> 1, vn = wid & 1;   // V-proj warp grid 4x2
    #pragma unroll 1
    for (int ci = 0; ci < 4; ci++) {
        // V proj: rows (128 + ci*64 + vm*16 .. +16) x cols (vn*64 .. +64)
        {
            const unsigned short* w0p = reinterpret_cast<const unsigned short*>(g_wc)
                                        + (128 + ci*64 + vm*16 + r4)*CCH;
            const unsigned short* w1p = w0p + 8*CCH;
            float vacc[8][4];
            #pragma unroll
            for (int nb = 0; nb < 8; nb++) { vacc[nb][0]=0.f; vacc[nb][1]=0.f; vacc[nb][2]=0.f; vacc[nb][3]=0.f; }
            #pragma unroll
            for (int kb = 0; kb < 16; kb++) {
                unsigned a[4];
                a[0] = *reinterpret_cast<const unsigned*>(w0p + kb*16 + c2);
                a[1] = *reinterpret_cast<const unsigned*>(w1p + kb*16 + c2);
                a[2] = *reinterpret_cast<const unsigned*>(w0p + kb*16 + c2 + 8);
                a[3] = *reinterpret_cast<const unsigned*>(w1p + kb*16 + c2 + 8);
                const int kr = kb*16 + c2;
                #pragma unroll
                for (int nb = 0; nb < 8; nb++) {
                    const int n = vn*64 + nb*8 + r4;
                    unsigned b0 = (unsigned)xsh[ kr   *LDX + n] | ((unsigned)xsh[(kr+1)*LDX + n] << 16);
                    unsigned b1 = (unsigned)xsh[(kr+8)*LDX + n] | ((unsigned)xsh[(kr+9)*LDX + n] << 16);
                    mma16816(vacc[nb], a, b0, b1);
                }
            }
            __syncthreads();   // previous O-phase done reading sV
            const int mg = 128 + ci*64 + vm*16;
            const float bias0 = g_bias[mg + r4], bias1 = g_bias[mg + r4 + 8];
            #pragma unroll
            for (int nb = 0; nb < 8; nb++) {
                *reinterpret_cast<unsigned*>(sV + (vm*16 + r4    )*LDQ + vn*64 + nb*8 + c2) =
                    pack_bf16(vacc[nb][0] + bias0, vacc[nb][1] + bias0);
                *reinterpret_cast<unsigned*>(sV + (vm*16 + r4 + 8)*LDQ + vn*64 + nb*8 + c2) =
                    pack_bf16(vacc[nb][2] + bias1, vacc[nb][3] + bias1);
            }
            __syncthreads();
        }

        // O phase for this chunk
        float oacc[8][4];
        #pragma unroll
        for (int nb = 0; nb < 8; nb++) { oacc[nb][0]=0.f; oacc[nb][1]=0.f; oacc[nb][2]=0.f; oacc[nb][3]=0.f; }
        #pragma unroll
        for (int kb = 0; kb < 8; kb++) {
            #pragma unroll
            for (int nb = 0; nb < 8; nb++) {
                unsigned b0 = *reinterpret_cast<const unsigned*>(sVh + (nb*8 + r4)*LDQ + kb*16 + c2);
                unsigned b1 = *reinterpret_cast<const unsigned*>(sVh + (nb*8 + r4)*LDQ + kb*16 + c2 + 8);
                mma16816(oacc[nb], ap[kb], b0, b1);
            }
        }

        // epilogue: y = gamma*O + x (fp32 x re-read; L2-hot)
        const int c0 = ci * 64;
        #pragma unroll
        for (int nb = 0; nb < 8; nb++) {
            int ch = c0 + nb*8 + c2;
            size_t base = ((size_t)(b*CCH + ch)*HH + h)*WW + w0;
            y[base + r4]          = g*oacc[nb][0] + x[base + r4];
            y[base + HW + r4]     = g*oacc[nb][1] + x[base + HW + r4];
            y[base + r4 + 8]      = g*oacc[nb][2] + x[base + r4 + 8];
            y[base + HW + r4 + 8] = g*oacc[nb][3] + x[base + HW + r4 + 8];
        }
    }
}

// ---------------- launch ----------------
extern "C" void kernel_launch(void* const* d_in, const int* in_sizes, int n_in,
                              void* d_out, int out_size) {
    const float* x     = (const float*)d_in[0];
    const float* wq    = (const float*)d_in[1];
    const float* bq    = (const float*)d_in[2];
    const float* wk    = (const float*)d_in[3];
    const float* bk    = (const float*)d_in[4];
    const float* wv    = (const float*)d_in[5];
    const float* bv    = (const float*)d_in[6];
    const float* gamma = (const float*)d_in[7];
    float* y = (float*)d_out;

    prep_w_kernel<<<(MTOT*CCH + 255)/256, 256>>>(wq, bq, wk, bk, wv, bv);

    cudaFuncSetAttribute(fused_kernel, cudaFuncAttributeMaxDynamicSharedMemorySize, FUSED_SMEM);
    fused_kernel<<<BATCH*HH, 256, FUSED_SMEM>>>(x, gamma, y);
}

// round 5
// speedup vs baseline: 2.4522x; 1.2734x over previous
#include <cuda_runtime.h>
#include <cuda_bf16.h>

#define BATCH 8
#define CCH   256
#define HH    128
#define WW    128
#define QKD   64
#define HW    (HH*WW)
#define MTOT  384

// ---------------- scratch ----------------
__device__ __align__(16) __nv_bfloat16 g_wc[MTOT*CCH];
__device__ float g_bias[MTOT];

// ---------------- prep: fuse weights + biases ----------------
__global__ void prep_w_kernel(const float* __restrict__ wq, const float* __restrict__ bq,
                              const float* __restrict__ wk, const float* __restrict__ bk,
                              const float* __restrict__ wv, const float* __restrict__ bv) {
    int i = blockIdx.x*blockDim.x + threadIdx.x;
    if (i < MTOT*CCH) {
        int row = i / CCH, col = i % CCH;
        float w;
        if (row < 64)       w = wq[row*CCH + col];
        else if (row < 128) w = wk[(row-64)*CCH + col];
        else                w = wv[(row-128)*CCH + col];
        g_wc[i] = __float2bfloat16(w);
    }
    if (i < MTOT) {
        float b;
        if (i < 64)       b = bq[i];
        else if (i < 128) b = bk[i-64];
        else              b = bv[i-128];
        g_bias[i] = b;
    }
}

// ---------------- fused kernel ----------------
#define LDX 136
#define LDQ 136
#define OFF_QK 69632
#define OFF_V  104448
#define FUSED_SMEM 121856

__device__ __forceinline__ void mma16816(float* d, const unsigned* a, unsigned b0, unsigned b1) {
    asm volatile("mma.sync.aligned.m16n8k16.row.col.f32.bf16.bf16.f32 "
        "{%0,%1,%2,%3}, {%4,%5,%6,%7}, {%8,%9}, {%0,%1,%2,%3};\n"
        : "+f"(d[0]), "+f"(d[1]), "+f"(d[2]), "+f"(d[3])
        : "r"(a[0]), "r"(a[1]), "r"(a[2]), "r"(a[3]), "r"(b0), "r"(b1));
}

#define LDSM4T(R0,R1,R2,R3,ADDR) \
    asm volatile("ldmatrix.sync.aligned.m8n8.x4.trans.shared.b16 {%0,%1,%2,%3}, [%4];\n" \
        : "=r"(R0), "=r"(R1), "=r"(R2), "=r"(R3) : "r"(ADDR))
#define LDSM4(R0,R1,R2,R3,ADDR) \
    asm volatile("ldmatrix.sync.aligned.m8n8.x4.shared.b16 {%0,%1,%2,%3}, [%4];\n" \
        : "=r"(R0), "=r"(R1), "=r"(R2), "=r"(R3) : "r"(ADDR))

__device__ __forceinline__ unsigned pack_bf16(float lo, float hi) {
    __nv_bfloat162 t = __floats2bfloat162_rn(lo, hi);
    return *reinterpret_cast<unsigned*>(&t);
}

__global__ void __launch_bounds__(256, 1) fused_kernel(const float* __restrict__ x,
                                                       const float* __restrict__ gamma,
                                                       float* __restrict__ y) {
    extern __shared__ char sm[];
    __nv_bfloat16* xs  = reinterpret_cast<__nv_bfloat16*>(sm);                // [256 ch][136] pixels
    __nv_bfloat16* sQK = reinterpret_cast<__nv_bfloat16*>(sm + OFF_QK);       // [128 ch][136] (Q:0-63, K:64-127)
    __nv_bfloat16* sV  = reinterpret_cast<__nv_bfloat16*>(sm + OFF_V);        // [64 ch][136]

    const int bh = blockIdx.x;
    const int b = bh >> 7, h = bh & 127;
    const int tid = threadIdx.x, wid = tid >> 5, lane = tid & 31;
    const int r4 = lane >> 2;
    const int c2 = (lane & 3) * 2;

    const unsigned ux = (unsigned)__cvta_generic_to_shared(xs);
    const unsigned uq = (unsigned)__cvta_generic_to_shared(sQK);
    const unsigned uk = uq + 64*LDQ*2;
    const unsigned uv = (unsigned)__cvta_generic_to_shared(sV);

    // LDSM lane-address components
    const int kq   = (lane & 7) + ((lane >> 3) & 1) * 8;   // B-trans: k row within 16
    const int nsel = (lane >> 4) & 1;                      // B-trans: which n8 of the pair
    const int ka   = (lane & 7) + ((lane >> 4) & 1) * 8;   // A-trans: k row within 16
    const int ma   = ((lane >> 3) & 1) * 8;                // A-trans: m8 select
    const int no   = (lane >> 4) & 1;                      // B non-trans: n8 select
    const int ko   = ((lane >> 3) & 1) * 8;                // B non-trans: k8 select

    const float* xb = x + (size_t)b*CCH*HW + h*WW;

    // ---- load x slice -> bf16 smem xs[channel][pixel] ----
    #pragma unroll
    for (int t = 0; t < 32; t++) {
        int idx = tid + t*256;
        int r = idx >> 5, c = idx & 31;
        float4 v = *reinterpret_cast<const float4*>(xb + (size_t)r*HW + c*4);
        __nv_bfloat162 lo = __floats2bfloat162_rn(v.x, v.y);
        __nv_bfloat162 hi = __floats2bfloat162_rn(v.z, v.w);
        uint2 u;
        u.x = *reinterpret_cast<unsigned*>(&lo);
        u.y = *reinterpret_cast<unsigned*>(&hi);
        *reinterpret_cast<uint2*>(xs + r*LDX + c*4) = u;
    }
    __syncthreads();

    // ---- proj Q,K: Wc rows 0..127 * xs + bias -> sQK[channel][pixel] ----
    {
        const int m0 = wid * 16;
        const unsigned short* w0p = reinterpret_cast<const unsigned short*>(g_wc) + (m0 + r4)*CCH;
        const unsigned short* w1p = w0p + 8*CCH;
        float acc[16][4];
        #pragma unroll
        for (int nb = 0; nb < 16; nb++) { acc[nb][0]=0.f; acc[nb][1]=0.f; acc[nb][2]=0.f; acc[nb][3]=0.f; }
        #pragma unroll
        for (int kb = 0; kb < 16; kb++) {
            unsigned a[4];
            a[0] = *reinterpret_cast<const unsigned*>(w0p + kb*16 + c2);
            a[1] = *reinterpret_cast<const unsigned*>(w1p + kb*16 + c2);
            a[2] = *reinterpret_cast<const unsigned*>(w0p + kb*16 + c2 + 8);
            a[3] = *reinterpret_cast<const unsigned*>(w1p + kb*16 + c2 + 8);
            const unsigned rb = ux + ((kb*16 + kq)*LDX)*2;
            #pragma unroll
            for (int njp = 0; njp < 8; njp++) {
                unsigned b0,b1,b2,b3;
                LDSM4T(b0,b1,b2,b3, rb + (njp*2 + nsel)*16);
                mma16816(acc[2*njp],   a, b0, b1);
                mma16816(acc[2*njp+1], a, b2, b3);
            }
        }
        const float bias0 = g_bias[m0 + r4], bias1 = g_bias[m0 + r4 + 8];
        #pragma unroll
        for (int nb = 0; nb < 16; nb++) {
            *reinterpret_cast<unsigned*>(sQK + (m0 + r4    )*LDQ + nb*8 + c2) =
                pack_bf16(acc[nb][0] + bias0, acc[nb][1] + bias0);
            *reinterpret_cast<unsigned*>(sQK + (m0 + r4 + 8)*LDQ + nb*8 + c2) =
                pack_bf16(acc[nb][2] + bias1, acc[nb][3] + bias1);
        }
    }
    __syncthreads();

    const int w0 = wid * 16;   // this warp's 16 query pixels

    // ---- S = Q^T K (per-warp 16 x 128) ----
    float sacc[16][4];
    #pragma unroll
    for (int nb = 0; nb < 16; nb++) { sacc[nb][0]=0.f; sacc[nb][1]=0.f; sacc[nb][2]=0.f; sacc[nb][3]=0.f; }

    #pragma unroll
    for (int kb = 0; kb < 4; kb++) {
        unsigned a[4];
        LDSM4T(a[0],a[1],a[2],a[3], uq + ((kb*16 + ka)*LDQ + w0 + ma)*2);
        const unsigned rb = uk + ((kb*16 + kq)*LDQ)*2;
        #pragma unroll
        for (int njp = 0; njp < 8; njp++) {
            unsigned b0,b1,b2,b3;
            LDSM4T(b0,b1,b2,b3, rb + (njp*2 + nsel)*16);
            mma16816(sacc[2*njp],   a, b0, b1);
            mma16816(sacc[2*njp+1], a, b2, b3);
        }
    }

    // ---- register softmax over 128 keys ----
    float mx0 = -1e30f, mx1 = -1e30f;
    #pragma unroll
    for (int nb = 0; nb < 16; nb++) {
        mx0 = fmaxf(mx0, fmaxf(sacc[nb][0], sacc[nb][1]));
        mx1 = fmaxf(mx1, fmaxf(sacc[nb][2], sacc[nb][3]));
    }
    mx0 = fmaxf(mx0, __shfl_xor_sync(0xffffffffu, mx0, 1));
    mx0 = fmaxf(mx0, __shfl_xor_sync(0xffffffffu, mx0, 2));
    mx1 = fmaxf(mx1, __shfl_xor_sync(0xffffffffu, mx1, 1));
    mx1 = fmaxf(mx1, __shfl_xor_sync(0xffffffffu, mx1, 2));
    float s0 = 0.f, s1 = 0.f;
    #pragma unroll
    for (int nb = 0; nb < 16; nb++) {
        sacc[nb][0] = __expf(sacc[nb][0] - mx0);
        sacc[nb][1] = __expf(sacc[nb][1] - mx0);
        sacc[nb][2] = __expf(sacc[nb][2] - mx1);
        sacc[nb][3] = __expf(sacc[nb][3] - mx1);
        s0 += sacc[nb][0] + sacc[nb][1];
        s1 += sacc[nb][2] + sacc[nb][3];
    }
    s0 += __shfl_xor_sync(0xffffffffu, s0, 1);
    s0 += __shfl_xor_sync(0xffffffffu, s0, 2);
    s1 += __shfl_xor_sync(0xffffffffu, s1, 1);
    s1 += __shfl_xor_sync(0xffffffffu, s1, 2);
    const float inv0 = 1.0f / s0, inv1 = 1.0f / s1;

    unsigned ap[8][4];
    #pragma unroll
    for (int kb = 0; kb < 8; kb++) {
        ap[kb][0] = pack_bf16(sacc[2*kb  ][0]*inv0, sacc[2*kb  ][1]*inv0);
        ap[kb][1] = pack_bf16(sacc[2*kb  ][2]*inv1, sacc[2*kb  ][3]*inv1);
        ap[kb][2] = pack_bf16(sacc[2*kb+1][0]*inv0, sacc[2*kb+1][1]*inv0);
        ap[kb][3] = pack_bf16(sacc[2*kb+1][2]*inv1, sacc[2*kb+1][3]*inv1);
    }

    const float g = gamma[0];

    // ---- 4 chunks of 64 V channels ----
    const int vm = wid >> 1, vn = wid & 1;
    #pragma unroll 1
    for (int ci = 0; ci < 4; ci++) {
        // V proj: rows (128 + ci*64 + vm*16..+16) x pixels (vn*64..+64)
        {
            const unsigned short* w0p = reinterpret_cast<const unsigned short*>(g_wc)
                                        + (128 + ci*64 + vm*16 + r4)*CCH;
            const unsigned short* w1p = w0p + 8*CCH;
            float vacc[8][4];
            #pragma unroll
            for (int nb = 0; nb < 8; nb++) { vacc[nb][0]=0.f; vacc[nb][1]=0.f; vacc[nb][2]=0.f; vacc[nb][3]=0.f; }
            #pragma unroll
            for (int kb = 0; kb < 16; kb++) {
                unsigned a[4];
                a[0] = *reinterpret_cast<const unsigned*>(w0p + kb*16 + c2);
                a[1] = *reinterpret_cast<const unsigned*>(w1p + kb*16 + c2);
                a[2] = *reinterpret_cast<const unsigned*>(w0p + kb*16 + c2 + 8);
                a[3] = *reinterpret_cast<const unsigned*>(w1p + kb*16 + c2 + 8);
                const unsigned rb = ux + ((kb*16 + kq)*LDX + vn*64)*2;
                #pragma unroll
                for (int njp = 0; njp < 4; njp++) {
                    unsigned b0,b1,b2,b3;
                    LDSM4T(b0,b1,b2,b3, rb + (njp*2 + nsel)*16);
                    mma16816(vacc[2*njp],   a, b0, b1);
                    mma16816(vacc[2*njp+1], a, b2, b3);
                }
            }
            __syncthreads();   // previous O-phase done reading sV
            const int mg = 128 + ci*64 + vm*16;
            const float bias0 = g_bias[mg + r4], bias1 = g_bias[mg + r4 + 8];
            #pragma unroll
            for (int nb = 0; nb < 8; nb++) {
                *reinterpret_cast<unsigned*>(sV + (vm*16 + r4    )*LDQ + vn*64 + nb*8 + c2) =
                    pack_bf16(vacc[nb][0] + bias0, vacc[nb][1] + bias0);
                *reinterpret_cast<unsigned*>(sV + (vm*16 + r4 + 8)*LDQ + vn*64 + nb*8 + c2) =
                    pack_bf16(vacc[nb][2] + bias1, vacc[nb][3] + bias1);
            }
            __syncthreads();
        }

        // O = attn * V^T for this chunk
        float oacc[8][4];
        #pragma unroll
        for (int nb = 0; nb < 8; nb++) { oacc[nb][0]=0.f; oacc[nb][1]=0.f; oacc[nb][2]=0.f; oacc[nb][3]=0.f; }
        #pragma unroll
        for (int kb = 0; kb < 8; kb++) {
            #pragma unroll
            for (int nbp = 0; nbp < 4; nbp++) {
                unsigned b0,b1,b2,b3;
                LDSM4(b0,b1,b2,b3,
                      uv + (((nbp*2 + no)*8 + (lane & 7))*LDQ + kb*16 + ko)*2);
                mma16816(oacc[2*nbp],   ap[kb], b0, b1);
                mma16816(oacc[2*nbp+1], ap[kb], b2, b3);
            }
        }

        // epilogue: y = gamma*O + x
        const int c0 = ci * 64;
        #pragma unroll
        for (int nb = 0; nb < 8; nb++) {
            int ch = c0 + nb*8 + c2;
            size_t base = ((size_t)(b*CCH + ch)*HH + h)*WW + w0;
            y[base + r4]          = g*oacc[nb][0] + x[base + r4];
            y[base + HW + r4]     = g*oacc[nb][1] + x[base + HW + r4];
            y[base + r4 + 8]      = g*oacc[nb][2] + x[base + r4 + 8];
            y[base + HW + r4 + 8] = g*oacc[nb][3] + x[base + HW + r4 + 8];
        }
    }
}

// ---------------- launch ----------------
extern "C" void kernel_launch(void* const* d_in, const int* in_sizes, int n_in,
                              void* d_out, int out_size) {
    const float* x     = (const float*)d_in[0];
    const float* wq    = (const float*)d_in[1];
    const float* bq    = (const float*)d_in[2];
    const float* wk    = (const float*)d_in[3];
    const float* bk    = (const float*)d_in[4];
    const float* wv    = (const float*)d_in[5];
    const float* bv    = (const float*)d_in[6];
    const float* gamma = (const float*)d_in[7];
    float* y = (float*)d_out;

    prep_w_kernel<<<(MTOT*CCH + 255)/256, 256>>>(wq, bq, wk, bk, wv, bv);

    cudaFuncSetAttribute(fused_kernel, cudaFuncAttributeMaxDynamicSharedMemorySize, FUSED_SMEM);
    fused_kernel<<<BATCH*HH, 256, FUSED_SMEM>>>(x, gamma, y);
}

// round 7
// speedup vs baseline: 3.5169x; 1.4342x over previous
#include <cuda_runtime.h>
#include <cuda_bf16.h>

#define BATCH 8
#define CCH   256
#define HH    128
#define WW    128
#define QKD   64
#define HW    (HH*WW)
#define MTOT  384

__device__ __forceinline__ unsigned pack_bf16(float lo, float hi) {
    __nv_bfloat162 t = __floats2bfloat162_rn(lo, hi);
    return *reinterpret_cast<unsigned*>(&t);
}

// ---------------- scratch ----------------
// fragment-ordered weights: 24 m16-tiles (0..7 = QK rows 0..127, 8..23 = V rows 128..383)
// layout: [tile][kb(16)][lane(32)] -> uint4 = {a0,a1,a2,a3} for mma.m16n8k16
__device__ __align__(16) uint4 g_wfrag[24*16*32];
__device__ float g_bias[MTOT];

// ---------------- prep ----------------
__global__ void prep_w_kernel(const float* __restrict__ wq, const float* __restrict__ bq,
                              const float* __restrict__ wk, const float* __restrict__ bk,
                              const float* __restrict__ wv, const float* __restrict__ bv) {
    int i = blockIdx.x*blockDim.x + threadIdx.x;
    if (i < 24*16*32) {
        int lane = i & 31, kb = (i >> 5) & 15, t = i >> 9;
        int r4 = lane >> 2, c2 = (lane & 3)*2;
        int m = (t < 8) ? t*16 : 128 + (t-8)*16;
        int k = kb*16 + c2;
        int r0 = m + r4, r1 = m + 8 + r4;
        auto fetch = [&](int row, int col) -> float {
            if (row < 64)  return wq[row*CCH + col];
            if (row < 128) return wk[(row-64)*CCH + col];
            return wv[(row-128)*CCH + col];
        };
        uint4 u;
        u.x = pack_bf16(fetch(r0, k),   fetch(r0, k+1));
        u.y = pack_bf16(fetch(r1, k),   fetch(r1, k+1));
        u.z = pack_bf16(fetch(r0, k+8), fetch(r0, k+9));
        u.w = pack_bf16(fetch(r1, k+8), fetch(r1, k+9));
        g_wfrag[i] = u;
    }
    if (i < MTOT) {
        float b;
        if (i < 64)       b = bq[i];
        else if (i < 128) b = bk[i-64];
        else              b = bv[i-128];
        g_bias[i] = b;
    }
}

// ---------------- fused kernel ----------------
#define LDX 136
#define LDQ 136
// xs: 256x136 bf16 = 69632 | sQK: 128x136 = 34816 | sV: 128x136 = 34816
#define OFF_QK 69632
#define OFF_V  104448
#define FUSED_SMEM 139264

__device__ __forceinline__ void mma16816(float* d, const unsigned* a, unsigned b0, unsigned b1) {
    asm volatile("mma.sync.aligned.m16n8k16.row.col.f32.bf16.bf16.f32 "
        "{%0,%1,%2,%3}, {%4,%5,%6,%7}, {%8,%9}, {%0,%1,%2,%3};\n"
        : "+f"(d[0]), "+f"(d[1]), "+f"(d[2]), "+f"(d[3])
        : "r"(a[0]), "r"(a[1]), "r"(a[2]), "r"(a[3]), "r"(b0), "r"(b1));
}

#define LDSM4T(R0,R1,R2,R3,ADDR) \
    asm volatile("ldmatrix.sync.aligned.m8n8.x4.trans.shared.b16 {%0,%1,%2,%3}, [%4];\n" \
        : "=r"(R0), "=r"(R1), "=r"(R2), "=r"(R3) : "r"(ADDR))
#define LDSM4(R0,R1,R2,R3,ADDR) \
    asm volatile("ldmatrix.sync.aligned.m8n8.x4.shared.b16 {%0,%1,%2,%3}, [%4];\n" \
        : "=r"(R0), "=r"(R1), "=r"(R2), "=r"(R3) : "r"(ADDR))

__global__ void __launch_bounds__(256, 1) fused_kernel(const float* __restrict__ x,
                                                       const float* __restrict__ gamma,
                                                       float* __restrict__ y) {
    extern __shared__ char sm[];
    __nv_bfloat16* xs  = reinterpret_cast<__nv_bfloat16*>(sm);
    __nv_bfloat16* sQK = reinterpret_cast<__nv_bfloat16*>(sm + OFF_QK);
    __nv_bfloat16* sV  = reinterpret_cast<__nv_bfloat16*>(sm + OFF_V);   // 128 rows

    const int bh = blockIdx.x;
    const int b = bh >> 7, h = bh & 127;
    const int tid = threadIdx.x, wid = tid >> 5, lane = tid & 31;
    const int r4 = lane >> 2;
    const int c2 = (lane & 3) * 2;

    const unsigned ux = (unsigned)__cvta_generic_to_shared(xs);
    const unsigned uq = (unsigned)__cvta_generic_to_shared(sQK);
    const unsigned uk = uq + 64*LDQ*2;
    const unsigned uv = (unsigned)__cvta_generic_to_shared(sV);

    const int kq   = (lane & 7) + ((lane >> 3) & 1) * 8;
    const int nsel = (lane >> 4) & 1;
    const int ka   = (lane & 7) + ((lane >> 4) & 1) * 8;
    const int ma   = ((lane >> 3) & 1) * 8;
    const int no   = (lane >> 4) & 1;
    const int ko   = ((lane >> 3) & 1) * 8;

    const float* xb = x + (size_t)b*CCH*HW + h*WW;

    // ---- load x slice -> bf16 smem xs[channel][pixel] ----
    #pragma unroll
    for (int t = 0; t < 32; t++) {
        int idx = tid + t*256;
        int r = idx >> 5, c = idx & 31;
        float4 v = *reinterpret_cast<const float4*>(xb + (size_t)r*HW + c*4);
        __nv_bfloat162 lo = __floats2bfloat162_rn(v.x, v.y);
        __nv_bfloat162 hi = __floats2bfloat162_rn(v.z, v.w);
        uint2 u;
        u.x = *reinterpret_cast<unsigned*>(&lo);
        u.y = *reinterpret_cast<unsigned*>(&hi);
        *reinterpret_cast<uint2*>(xs + r*LDX + c*4) = u;
    }
    __syncthreads();

    // ---- proj Q,K: Wc rows 0..127 * xs + bias -> sQK[channel][pixel] ----
    {
        const int m0 = wid * 16;
        const uint4* wf = g_wfrag + wid*512 + lane;
        float acc[16][4];
        #pragma unroll
        for (int nb = 0; nb < 16; nb++) { acc[nb][0]=0.f; acc[nb][1]=0.f; acc[nb][2]=0.f; acc[nb][3]=0.f; }
        #pragma unroll
        for (int kb = 0; kb < 16; kb++) {
            uint4 aw = wf[kb*32];
            unsigned a[4] = {aw.x, aw.y, aw.z, aw.w};
            const unsigned rb = ux + ((kb*16 + kq)*LDX)*2;
            #pragma unroll
            for (int njp = 0; njp < 8; njp++) {
                unsigned b0,b1,b2,b3;
                LDSM4T(b0,b1,b2,b3, rb + (njp*2 + nsel)*16);
                mma16816(acc[2*njp],   a, b0, b1);
                mma16816(acc[2*njp+1], a, b2, b3);
            }
        }
        const float bias0 = g_bias[m0 + r4], bias1 = g_bias[m0 + r4 + 8];
        #pragma unroll
        for (int nb = 0; nb < 16; nb++) {
            *reinterpret_cast<unsigned*>(sQK + (m0 + r4    )*LDQ + nb*8 + c2) =
                pack_bf16(acc[nb][0] + bias0, acc[nb][1] + bias0);
            *reinterpret_cast<unsigned*>(sQK + (m0 + r4 + 8)*LDQ + nb*8 + c2) =
                pack_bf16(acc[nb][2] + bias1, acc[nb][3] + bias1);
        }
    }
    __syncthreads();

    const int w0 = wid * 16;

    // ---- S = Q^T K (per-warp 16 x 128) ----
    float sacc[16][4];
    #pragma unroll
    for (int nb = 0; nb < 16; nb++) { sacc[nb][0]=0.f; sacc[nb][1]=0.f; sacc[nb][2]=0.f; sacc[nb][3]=0.f; }

    #pragma unroll
    for (int kb = 0; kb < 4; kb++) {
        unsigned a[4];
        LDSM4T(a[0],a[1],a[2],a[3], uq + ((kb*16 + ka)*LDQ + w0 + ma)*2);
        const unsigned rb = uk + ((kb*16 + kq)*LDQ)*2;
        #pragma unroll
        for (int njp = 0; njp < 8; njp++) {
            unsigned b0,b1,b2,b3;
            LDSM4T(b0,b1,b2,b3, rb + (njp*2 + nsel)*16);
            mma16816(sacc[2*njp],   a, b0, b1);
            mma16816(sacc[2*njp+1], a, b2, b3);
        }
    }

    // ---- register softmax ----
    float mx0 = -1e30f, mx1 = -1e30f;
    #pragma unroll
    for (int nb = 0; nb < 16; nb++) {
        mx0 = fmaxf(mx0, fmaxf(sacc[nb][0], sacc[nb][1]));
        mx1 = fmaxf(mx1, fmaxf(sacc[nb][2], sacc[nb][3]));
    }
    mx0 = fmaxf(mx0, __shfl_xor_sync(0xffffffffu, mx0, 1));
    mx0 = fmaxf(mx0, __shfl_xor_sync(0xffffffffu, mx0, 2));
    mx1 = fmaxf(mx1, __shfl_xor_sync(0xffffffffu, mx1, 1));
    mx1 = fmaxf(mx1, __shfl_xor_sync(0xffffffffu, mx1, 2));
    float s0 = 0.f, s1 = 0.f;
    #pragma unroll
    for (int nb = 0; nb < 16; nb++) {
        sacc[nb][0] = __expf(sacc[nb][0] - mx0);
        sacc[nb][1] = __expf(sacc[nb][1] - mx0);
        sacc[nb][2] = __expf(sacc[nb][2] - mx1);
        sacc[nb][3] = __expf(sacc[nb][3] - mx1);
        s0 += sacc[nb][0] + sacc[nb][1];
        s1 += sacc[nb][2] + sacc[nb][3];
    }
    s0 += __shfl_xor_sync(0xffffffffu, s0, 1);
    s0 += __shfl_xor_sync(0xffffffffu, s0, 2);
    s1 += __shfl_xor_sync(0xffffffffu, s1, 1);
    s1 += __shfl_xor_sync(0xffffffffu, s1, 2);
    const float inv0 = 1.0f / s0, inv1 = 1.0f / s1;

    unsigned ap[8][4];
    #pragma unroll
    for (int kb = 0; kb < 8; kb++) {
        ap[kb][0] = pack_bf16(sacc[2*kb  ][0]*inv0, sacc[2*kb  ][1]*inv0);
        ap[kb][1] = pack_bf16(sacc[2*kb  ][2]*inv1, sacc[2*kb  ][3]*inv1);
        ap[kb][2] = pack_bf16(sacc[2*kb+1][0]*inv0, sacc[2*kb+1][1]*inv0);
        ap[kb][3] = pack_bf16(sacc[2*kb+1][2]*inv1, sacc[2*kb+1][3]*inv1);
    }

    const float g = gamma[0];

    // ---- V proj + O, 2 groups of 2 chunks (B frags shared within group) ----
    const int vm = wid >> 1, vn = wid & 1;
    #pragma unroll 1
    for (int gi = 0; gi < 2; gi++) {
        // V proj: two chunks ci0 = gi*2, ci1 = gi*2+1; warp rows vm*16, pixels vn*64..+64
        {
            const uint4* wf0 = g_wfrag + (8 + (gi*2    )*4 + vm)*512 + lane;
            const uint4* wf1 = g_wfrag + (8 + (gi*2 + 1)*4 + vm)*512 + lane;
            float vacc[2][8][4];
            #pragma unroll
            for (int cc = 0; cc < 2; cc++)
                #pragma unroll
                for (int nb = 0; nb < 8; nb++) {
                    vacc[cc][nb][0]=0.f; vacc[cc][nb][1]=0.f;
                    vacc[cc][nb][2]=0.f; vacc[cc][nb][3]=0.f;
                }
            #pragma unroll
            for (int kb = 0; kb < 16; kb++) {
                uint4 aw0 = wf0[kb*32];
                uint4 aw1 = wf1[kb*32];
                unsigned a0[4] = {aw0.x, aw0.y, aw0.z, aw0.w};
                unsigned a1[4] = {aw1.x, aw1.y, aw1.z, aw1.w};
                const unsigned rb = ux + ((kb*16 + kq)*LDX + vn*64)*2;
                #pragma unroll
                for (int njp = 0; njp < 4; njp++) {
                    unsigned b0,b1,b2,b3;
                    LDSM4T(b0,b1,b2,b3, rb + (njp*2 + nsel)*16);
                    mma16816(vacc[0][2*njp],   a0, b0, b1);
                    mma16816(vacc[0][2*njp+1], a0, b2, b3);
                    mma16816(vacc[1][2*njp],   a1, b0, b1);
                    mma16816(vacc[1][2*njp+1], a1, b2, b3);
                }
            }
            __syncthreads();   // prior O-phase done reading sV
            #pragma unroll
            for (int cc = 0; cc < 2; cc++) {
                const int mg = 128 + (gi*2 + cc)*64 + vm*16;
                const float bias0 = g_bias[mg + r4], bias1 = g_bias[mg + r4 + 8];
                __nv_bfloat16* sVc = sV + cc*64*LDQ;
                #pragma unroll
                for (int nb = 0; nb < 8; nb++) {
                    *reinterpret_cast<unsigned*>(sVc + (vm*16 + r4    )*LDQ + vn*64 + nb*8 + c2) =
                        pack_bf16(vacc[cc][nb][0] + bias0, vacc[cc][nb][1] + bias0);
                    *reinterpret_cast<unsigned*>(sVc + (vm*16 + r4 + 8)*LDQ + vn*64 + nb*8 + c2) =
                        pack_bf16(vacc[cc][nb][2] + bias1, vacc[cc][nb][3] + bias1);
                }
            }
            __syncthreads();
        }

        // O = attn * V^T, 2 chunks
        #pragma unroll 1
        for (int cc = 0; cc < 2; cc++) {
            const unsigned uvc = uv + cc*64*LDQ*2;
            float oacc[8][4];
            #pragma unroll
            for (int nb = 0; nb < 8; nb++) { oacc[nb][0]=0.f; oacc[nb][1]=0.f; oacc[nb][2]=0.f; oacc[nb][3]=0.f; }
            #pragma unroll
            for (int kb = 0; kb < 8; kb++) {
                #pragma unroll
                for (int nbp = 0; nbp < 4; nbp++) {
                    unsigned b0,b1,b2,b3;
                    LDSM4(b0,b1,b2,b3,
                          uvc + (((nbp*2 + no)*8 + (lane & 7))*LDQ + kb*16 + ko)*2);
                    mma16816(oacc[2*nbp],   ap[kb], b0, b1);
                    mma16816(oacc[2*nbp+1], ap[kb], b2, b3);
                }
            }

            const int c0 = (gi*2 + cc) * 64;
            #pragma unroll
            for (int nb = 0; nb < 8; nb++) {
                int ch = c0 + nb*8 + c2;
                size_t base = ((size_t)(b*CCH + ch)*HH + h)*WW + w0;
                y[base + r4]          = g*oacc[nb][0] + x[base + r4];
                y[base + HW + r4]     = g*oacc[nb][1] + x[base + HW + r4];
                y[base + r4 + 8]      = g*oacc[nb][2] + x[base + r4 + 8];
                y[base + HW + r4 + 8] = g*oacc[nb][3] + x[base + HW + r4 + 8];
            }
        }
    }
}

// ---------------- launch ----------------
extern "C" void kernel_launch(void* const* d_in, const int* in_sizes, int n_in,
                              void* d_out, int out_size) {
    const float* x     = (const float*)d_in[0];
    const float* wq    = (const float*)d_in[1];
    const float* bq    = (const float*)d_in[2];
    const float* wk    = (const float*)d_in[3];
    const float* bk    = (const float*)d_in[4];
    const float* wv    = (const float*)d_in[5];
    const float* bv    = (const float*)d_in[6];
    const float* gamma = (const float*)d_in[7];
    float* y = (float*)d_out;

    prep_w_kernel<<<48, 256>>>(wq, bq, wk, bk, wv, bv);

    cudaFuncSetAttribute(fused_kernel, cudaFuncAttributeMaxDynamicSharedMemorySize, FUSED_SMEM);
    fused_kernel<<<BATCH*HH, 256, FUSED_SMEM>>>(x, gamma, y);
}

// round 11
// speedup vs baseline: 3.7492x; 1.0660x over previous
#include <cuda_runtime.h>
#include <cuda_bf16.h>

#define BATCH 8
#define CCH   256
#define HH    128
#define WW    128
#define QKD   64
#define HW    (HH*WW)
#define MTOT  384

__device__ __forceinline__ unsigned pack_bf16(float lo, float hi) {
    __nv_bfloat162 t = __floats2bfloat162_rn(lo, hi);
    return *reinterpret_cast<unsigned*>(&t);
}

// ---------------- scratch ----------------
// fragment-ordered weights: 24 m16-tiles (0..7 = QK rows 0..127, 8..23 = V rows 128..383)
// layout: [tile][kb(16)][lane(32)] -> uint4 = {a0,a1,a2,a3} for mma.m16n8k16
__device__ __align__(16) uint4 g_wfrag[24*16*32];
__device__ float g_bias[MTOT];

// ---------------- prep ----------------
__global__ void prep_w_kernel(const float* __restrict__ wq, const float* __restrict__ bq,
                              const float* __restrict__ wk, const float* __restrict__ bk,
                              const float* __restrict__ wv, const float* __restrict__ bv) {
    int i = blockIdx.x*blockDim.x + threadIdx.x;
    if (i < 24*16*32) {
        int lane = i & 31, kb = (i >> 5) & 15, t = i >> 9;
        int r4 = lane >> 2, c2 = (lane & 3)*2;
        int m = (t < 8) ? t*16 : 128 + (t-8)*16;
        int k = kb*16 + c2;
        int r0 = m + r4, r1 = m + 8 + r4;
        auto fetch = [&](int row, int col) -> float {
            if (row < 64)  return wq[row*CCH + col];
            if (row < 128) return wk[(row-64)*CCH + col];
            return wv[(row-128)*CCH + col];
        };
        uint4 u;
        u.x = pack_bf16(fetch(r0, k),   fetch(r0, k+1));
        u.y = pack_bf16(fetch(r1, k),   fetch(r1, k+1));
        u.z = pack_bf16(fetch(r0, k+8), fetch(r0, k+9));
        u.w = pack_bf16(fetch(r1, k+8), fetch(r1, k+9));
        g_wfrag[i] = u;
    }
    if (i < MTOT) {
        float b;
        if (i < 64)       b = bq[i];
        else if (i < 128) b = bk[i-64];
        else              b = bv[i-128];
        g_bias[i] = b;
    }
}

// ---------------- fused kernel ----------------
#define LDX 136
#define LDQ 136
#define LDO 132
// xs: 256x136 bf16 = 69632 | sQK: 128x136 = 34816 (reused as fp32 O staging 64x132) | sV: 128x136 = 34816
#define OFF_QK 69632
#define OFF_V  104448
#define FUSED_SMEM 139264

__device__ __forceinline__ void mma16816(float* d, const unsigned* a, unsigned b0, unsigned b1) {
    asm volatile("mma.sync.aligned.m16n8k16.row.col.f32.bf16.bf16.f32 "
        "{%0,%1,%2,%3}, {%4,%5,%6,%7}, {%8,%9}, {%0,%1,%2,%3};\n"
        : "+f"(d[0]), "+f"(d[1]), "+f"(d[2]), "+f"(d[3])
        : "r"(a[0]), "r"(a[1]), "r"(a[2]), "r"(a[3]), "r"(b0), "r"(b1));
}

#define LDSM4T(R0,R1,R2,R3,ADDR) \
    asm volatile("ldmatrix.sync.aligned.m8n8.x4.trans.shared.b16 {%0,%1,%2,%3}, [%4];\n" \
        : "=r"(R0), "=r"(R1), "=r"(R2), "=r"(R3) : "r"(ADDR))
#define LDSM4(R0,R1,R2,R3,ADDR) \
    asm volatile("ldmatrix.sync.aligned.m8n8.x4.shared.b16 {%0,%1,%2,%3}, [%4];\n" \
        : "=r"(R0), "=r"(R1), "=r"(R2), "=r"(R3) : "r"(ADDR))

__global__ void __launch_bounds__(256, 1) fused_kernel(const float* __restrict__ x,
                                                       const float* __restrict__ gamma,
                                                       float* __restrict__ y) {
    extern __shared__ char sm[];
    __nv_bfloat16* xs  = reinterpret_cast<__nv_bfloat16*>(sm);
    __nv_bfloat16* sQK = reinterpret_cast<__nv_bfloat16*>(sm + OFF_QK);
    __nv_bfloat16* sV  = reinterpret_cast<__nv_bfloat16*>(sm + OFF_V);   // 128 rows
    float*         sO  = reinterpret_cast<float*>(sm + OFF_QK);          // staging, reuses sQK

    const int bh = blockIdx.x;
    const int b = bh >> 7, h = bh & 127;
    const int tid = threadIdx.x, wid = tid >> 5, lane = tid & 31;
    const int r4 = lane >> 2;
    const int c2 = (lane & 3) * 2;

    const unsigned ux = (unsigned)__cvta_generic_to_shared(xs);
    const unsigned uq = (unsigned)__cvta_generic_to_shared(sQK);
    const unsigned uk = uq + 64*LDQ*2;
    const unsigned uv = (unsigned)__cvta_generic_to_shared(sV);

    const int kq   = (lane & 7) + ((lane >> 3) & 1) * 8;
    const int nsel = (lane >> 4) & 1;
    const int ka   = (lane & 7) + ((lane >> 4) & 1) * 8;
    const int ma   = ((lane >> 3) & 1) * 8;
    const int no   = (lane >> 4) & 1;
    const int ko   = ((lane >> 3) & 1) * 8;

    const float* xb = x + (size_t)b*CCH*HW + h*WW;

    // ---- load x slice -> bf16 smem xs[channel][pixel] ----
    #pragma unroll
    for (int t = 0; t < 32; t++) {
        int idx = tid + t*256;
        int r = idx >> 5, c = idx & 31;
        float4 v = *reinterpret_cast<const float4*>(xb + (size_t)r*HW + c*4);
        __nv_bfloat162 lo = __floats2bfloat162_rn(v.x, v.y);
        __nv_bfloat162 hi = __floats2bfloat162_rn(v.z, v.w);
        uint2 u;
        u.x = *reinterpret_cast<unsigned*>(&lo);
        u.y = *reinterpret_cast<unsigned*>(&hi);
        *reinterpret_cast<uint2*>(xs + r*LDX + c*4) = u;
    }
    __syncthreads();

    // ---- proj Q,K: warp = (2 m-tiles, 64-pixel half) ----
    {
        const int mi = wid >> 1, ph = wid & 1;
        const uint4* wf0 = g_wfrag + (mi*2    )*512 + lane;
        const uint4* wf1 = g_wfrag + (mi*2 + 1)*512 + lane;
        float acc[2][8][4];
        #pragma unroll
        for (int tt = 0; tt < 2; tt++)
            #pragma unroll
            for (int nb = 0; nb < 8; nb++) {
                acc[tt][nb][0]=0.f; acc[tt][nb][1]=0.f; acc[tt][nb][2]=0.f; acc[tt][nb][3]=0.f;
            }
        #pragma unroll
        for (int kb = 0; kb < 16; kb++) {
            uint4 aw0 = wf0[kb*32];
            uint4 aw1 = wf1[kb*32];
            unsigned a0[4] = {aw0.x, aw0.y, aw0.z, aw0.w};
            unsigned a1[4] = {aw1.x, aw1.y, aw1.z, aw1.w};
            const unsigned rb = ux + ((kb*16 + kq)*LDX + ph*64)*2;
            #pragma unroll
            for (int njp = 0; njp < 4; njp++) {
                unsigned b0,b1,b2,b3;
                LDSM4T(b0,b1,b2,b3, rb + (njp*2 + nsel)*16);
                mma16816(acc[0][2*njp],   a0, b0, b1);
                mma16816(acc[0][2*njp+1], a0, b2, b3);
                mma16816(acc[1][2*njp],   a1, b0, b1);
                mma16816(acc[1][2*njp+1], a1, b2, b3);
            }
        }
        #pragma unroll
        for (int tt = 0; tt < 2; tt++) {
            const int m0 = (mi*2 + tt)*16;
            const float bias0 = g_bias[m0 + r4], bias1 = g_bias[m0 + r4 + 8];
            #pragma unroll
            for (int nb = 0; nb < 8; nb++) {
                const int col = ph*64 + nb*8 + c2;
                *reinterpret_cast<unsigned*>(sQK + (m0 + r4    )*LDQ + col) =
                    pack_bf16(acc[tt][nb][0] + bias0, acc[tt][nb][1] + bias0);
                *reinterpret_cast<unsigned*>(sQK + (m0 + r4 + 8)*LDQ + col) =
                    pack_bf16(acc[tt][nb][2] + bias1, acc[tt][nb][3] + bias1);
            }
        }
    }
    __syncthreads();

    const int w0 = wid * 16;

    // ---- S = Q^T K (per-warp 16 x 128) ----
    float sacc[16][4];
    #pragma unroll
    for (int nb = 0; nb < 16; nb++) { sacc[nb][0]=0.f; sacc[nb][1]=0.f; sacc[nb][2]=0.f; sacc[nb][3]=0.f; }

    #pragma unroll
    for (int kb = 0; kb < 4; kb++) {
        unsigned a[4];
        LDSM4T(a[0],a[1],a[2],a[3], uq + ((kb*16 + ka)*LDQ + w0 + ma)*2);
        const unsigned rb = uk + ((kb*16 + kq)*LDQ)*2;
        #pragma unroll
        for (int njp = 0; njp < 8; njp++) {
            unsigned b0,b1,b2,b3;
            LDSM4T(b0,b1,b2,b3, rb + (njp*2 + nsel)*16);
            mma16816(sacc[2*njp],   a, b0, b1);
            mma16816(sacc[2*njp+1], a, b2, b3);
        }
    }

    // ---- register softmax ----
    float mx0 = -1e30f, mx1 = -1e30f;
    #pragma unroll
    for (int nb = 0; nb < 16; nb++) {
        mx0 = fmaxf(mx0, fmaxf(sacc[nb][0], sacc[nb][1]));
        mx1 = fmaxf(mx1, fmaxf(sacc[nb][2], sacc[nb][3]));
    }
    mx0 = fmaxf(mx0, __shfl_xor_sync(0xffffffffu, mx0, 1));
    mx0 = fmaxf(mx0, __shfl_xor_sync(0xffffffffu, mx0, 2));
    mx1 = fmaxf(mx1, __shfl_xor_sync(0xffffffffu, mx1, 1));
    mx1 = fmaxf(mx1, __shfl_xor_sync(0xffffffffu, mx1, 2));
    float s0 = 0.f, s1 = 0.f;
    #pragma unroll
    for (int nb = 0; nb < 16; nb++) {
        sacc[nb][0] = __expf(sacc[nb][0] - mx0);
        sacc[nb][1] = __expf(sacc[nb][1] - mx0);
        sacc[nb][2] = __expf(sacc[nb][2] - mx1);
        sacc[nb][3] = __expf(sacc[nb][3] - mx1);
        s0 += sacc[nb][0] + sacc[nb][1];
        s1 += sacc[nb][2] + sacc[nb][3];
    }
    s0 += __shfl_xor_sync(0xffffffffu, s0, 1);
    s0 += __shfl_xor_sync(0xffffffffu, s0, 2);
    s1 += __shfl_xor_sync(0xffffffffu, s1, 1);
    s1 += __shfl_xor_sync(0xffffffffu, s1, 2);
    const float inv0 = 1.0f / s0, inv1 = 1.0f / s1;

    unsigned ap[8][4];
    #pragma unroll
    for (int kb = 0; kb < 8; kb++) {
        ap[kb][0] = pack_bf16(sacc[2*kb  ][0]*inv0, sacc[2*kb  ][1]*inv0);
        ap[kb][1] = pack_bf16(sacc[2*kb  ][2]*inv1, sacc[2*kb  ][3]*inv1);
        ap[kb][2] = pack_bf16(sacc[2*kb+1][0]*inv0, sacc[2*kb+1][1]*inv0);
        ap[kb][3] = pack_bf16(sacc[2*kb+1][2]*inv1, sacc[2*kb+1][3]*inv1);
    }

    const float g = gamma[0];

    // ---- V proj + O, 2 groups of 2 chunks ----
    const int vm = wid >> 1, vn = wid & 1;
    #pragma unroll 1
    for (int gi = 0; gi < 2; gi++) {
        // V proj
        {
            const uint4* wf0 = g_wfrag + (8 + (gi*2    )*4 + vm)*512 + lane;
            const uint4* wf1 = g_wfrag + (8 + (gi*2 + 1)*4 + vm)*512 + lane;
            float vacc[2][8][4];
            #pragma unroll
            for (int cc = 0; cc < 2; cc++)
                #pragma unroll
                for (int nb = 0; nb < 8; nb++) {
                    vacc[cc][nb][0]=0.f; vacc[cc][nb][1]=0.f;
                    vacc[cc][nb][2]=0.f; vacc[cc][nb][3]=0.f;
                }
            #pragma unroll
            for (int kb = 0; kb < 16; kb++) {
                uint4 aw0 = wf0[kb*32];
                uint4 aw1 = wf1[kb*32];
                unsigned a0[4] = {aw0.x, aw0.y, aw0.z, aw0.w};
                unsigned a1[4] = {aw1.x, aw1.y, aw1.z, aw1.w};
                const unsigned rb = ux + ((kb*16 + kq)*LDX + vn*64)*2;
                #pragma unroll
                for (int njp = 0; njp < 4; njp++) {
                    unsigned b0,b1,b2,b3;
                    LDSM4T(b0,b1,b2,b3, rb + (njp*2 + nsel)*16);
                    mma16816(vacc[0][2*njp],   a0, b0, b1);
                    mma16816(vacc[0][2*njp+1], a0, b2, b3);
                    mma16816(vacc[1][2*njp],   a1, b0, b1);
                    mma16816(vacc[1][2*njp+1], a1, b2, b3);
                }
            }
            __syncthreads();   // prior O-phase / epilogue done with sV and sO
            #pragma unroll
            for (int cc = 0; cc < 2; cc++) {
                const int mg = 128 + (gi*2 + cc)*64 + vm*16;
                const float bias0 = g_bias[mg + r4], bias1 = g_bias[mg + r4 + 8];
                __nv_bfloat16* sVc = sV + cc*64*LDQ;
                #pragma unroll
                for (int nb = 0; nb < 8; nb++) {
                    *reinterpret_cast<unsigned*>(sVc + (vm*16 + r4    )*LDQ + vn*64 + nb*8 + c2) =
                        pack_bf16(vacc[cc][nb][0] + bias0, vacc[cc][nb][1] + bias0);
                    *reinterpret_cast<unsigned*>(sVc + (vm*16 + r4 + 8)*LDQ + vn*64 + nb*8 + c2) =
                        pack_bf16(vacc[cc][nb][2] + bias1, vacc[cc][nb][3] + bias1);
                }
            }
            __syncthreads();
        }

        // O = attn * V^T, 2 chunks
        #pragma unroll 1
        for (int cc = 0; cc < 2; cc++) {
            const unsigned uvc = uv + cc*64*LDQ*2;
            float oacc[8][4];
            #pragma unroll
            for (int nb = 0; nb < 8; nb++) { oacc[nb][0]=0.f; oacc[nb][1]=0.f; oacc[nb][2]=0.f; oacc[nb][3]=0.f; }
            #pragma unroll
            for (int kb = 0; kb < 8; kb++) {
                #pragma unroll
                for (int nbp = 0; nbp < 4; nbp++) {
                    unsigned b0,b1,b2,b3;
                    LDSM4(b0,b1,b2,b3,
                          uvc + (((nbp*2 + no)*8 + (lane & 7))*LDQ + kb*16 + ko)*2);
                    mma16816(oacc[2*nbp],   ap[kb], b0, b1);
                    mma16816(oacc[2*nbp+1], ap[kb], b2, b3);
                }
            }

            // epilogue: stage O as fp32 [ch][pixel] in sO, then coalesced float4 I/O
            __syncthreads();   // prior epilogue readers done with sO
            #pragma unroll
            for (int nb = 0; nb < 8; nb++) {
                const int chl = nb*8 + c2;
                sO[ chl   *LDO + w0 + r4    ] = oacc[nb][0];
                sO[(chl+1)*LDO + w0 + r4    ] = oacc[nb][1];
                sO[ chl   *LDO + w0 + r4 + 8] = oacc[nb][2];
                sO[(chl+1)*LDO + w0 + r4 + 8] = oacc[nb][3];
            }
            __syncthreads();

            const int c0 = (gi*2 + cc) * 64;
            #pragma unroll
            for (int t = 0; t < 8; t++) {
                int idx = tid + t*256;            // 2048 float4 = 64 ch x 32
                int r = idx >> 5, cq = idx & 31;
                float4 o = *reinterpret_cast<const float4*>(sO + r*LDO + cq*4);
                size_t base = ((size_t)(b*CCH + c0 + r)*HH + h)*WW + cq*4;
                float4 xv = *reinterpret_cast<const float4*>(x + base);
                float4 ov;
                ov.x = g*o.x + xv.x; ov.y = g*o.y + xv.y;
                ov.z = g*o.z + xv.z; ov.w = g*o.w + xv.w;
                *reinterpret_cast<float4*>(y + base) = ov;
            }
        }
    }
}

// ---------------- launch ----------------
extern "C" void kernel_launch(void* const* d_in, const int* in_sizes, int n_in,
                              void* d_out, int out_size) {
    const float* x     = (const float*)d_in[0];
    const float* wq    = (const float*)d_in[1];
    const float* bq    = (const float*)d_in[2];
    const float* wk    = (const float*)d_in[3];
    const float* bk    = (const float*)d_in[4];
    const float* wv    = (const float*)d_in[5];
    const float* bv    = (const float*)d_in[6];
    const float* gamma = (const float*)d_in[7];
    float* y = (float*)d_out;

    prep_w_kernel<<<48, 256>>>(wq, bq, wk, bk, wv, bv);

    cudaFuncSetAttribute(fused_kernel, cudaFuncAttributeMaxDynamicSharedMemorySize, FUSED_SMEM);
    fused_kernel<<<BATCH*HH, 256, FUSED_SMEM>>>(x, gamma, y);
}